// round 1
// baseline (speedup 1.0000x reference)
#include <cuda_runtime.h>
#include <math.h>

// ---------------------------------------------------------------------------
// Problem constants
// ---------------------------------------------------------------------------
#define DIMD  1024
#define BATCH 8
#define SEQ   4096
#define MTOT  (BATCH * SEQ)        // 32768 rows for the projection GEMMs
#define NSCAN 128                  // persistent scan CTAs (<= 148 SMs, all co-resident)
#define EPER  (DIMD / NSCAN)       // 8 output dims owned per scan CTA

// ---------------------------------------------------------------------------
// Scratch (device-global; no allocation allowed in kernel_launch)
// ---------------------------------------------------------------------------
__device__ float g_inp   [(size_t)MTOT * DIMD];
__device__ float g_gate  [(size_t)MTOT * DIMD];
__device__ float g_u     [(size_t)MTOT * DIMD];
__device__ float g_states[(size_t)MTOT * DIMD];
__device__ float g_s[2][BATCH * DIMD];   // ping-pong recurrent state
__device__ unsigned g_counter;            // grid barrier counter (monotonic per launch)

// ---------------------------------------------------------------------------
// Init kernel: re-zero state + barrier counter every launch (graph replays!)
// ---------------------------------------------------------------------------
__global__ void init_kernel() {
    int t = blockIdx.x * blockDim.x + threadIdx.x;
    if (t < BATCH * DIMD) { g_s[0][t] = 0.f; g_s[1][t] = 0.f; }
    if (t == 0) g_counter = 0u;
}

// ---------------------------------------------------------------------------
// fp32 GEMM (NT): C[m][n] = sum_k X[m][k] * W[n][k] (+ bias[n]) (+ sigmoid)
// BM=BN=128, BK=16, 256 threads, 8x8 register tile.
// ---------------------------------------------------------------------------
#define BM 128
#define BN 128
#define BK 16
#define GP 132   // padded SMEM pitch (floats); 132*4 % 16 == 0 -> float4 aligned

template <int EPI>   // 0 = none, 1 = sigmoid
__global__ __launch_bounds__(256, 2)
void gemm_nt(const float* __restrict__ X, const float* __restrict__ W,
             const float* __restrict__ bias, float* __restrict__ C,
             int M, int N, int K)
{
    __shared__ float As[BK][GP];
    __shared__ float Bs[BK][GP];

    const int tid = threadIdx.x;
    const int bm  = blockIdx.y * BM;
    const int bn  = blockIdx.x * BN;

    const int lr = tid >> 2;          // 0..63 (tile row for loads)
    const int lc = (tid & 3) << 2;    // 0,4,8,12 (k-subcolumn, float4)

    const float* Xp = X + (size_t)(bm + lr) * K + lc;
    const float* Wp = W + (size_t)(bn + lr) * K + lc;

    const int tRow = (tid >> 4) << 3; // 0..120, micro-tile M base
    const int tCol = (tid & 15) << 3; // 0..120, micro-tile N base

    float acc[8][8];
#pragma unroll
    for (int i = 0; i < 8; i++)
#pragma unroll
        for (int j = 0; j < 8; j++) acc[i][j] = 0.f;

    for (int k0 = 0; k0 < K; k0 += BK) {
#pragma unroll
        for (int it = 0; it < 2; it++) {
            float4 av = *(const float4*)(Xp + (size_t)(64 * it) * K + k0);
            float4 bv = *(const float4*)(Wp + (size_t)(64 * it) * K + k0);
            int r = lr + 64 * it;
            As[lc + 0][r] = av.x; As[lc + 1][r] = av.y;
            As[lc + 2][r] = av.z; As[lc + 3][r] = av.w;
            Bs[lc + 0][r] = bv.x; Bs[lc + 1][r] = bv.y;
            Bs[lc + 2][r] = bv.z; Bs[lc + 3][r] = bv.w;
        }
        __syncthreads();

#pragma unroll
        for (int k = 0; k < BK; k++) {
            float4 a0 = *(const float4*)&As[k][tRow];
            float4 a1 = *(const float4*)&As[k][tRow + 4];
            float4 b0 = *(const float4*)&Bs[k][tCol];
            float4 b1 = *(const float4*)&Bs[k][tCol + 4];
            float a[8] = {a0.x, a0.y, a0.z, a0.w, a1.x, a1.y, a1.z, a1.w};
            float b[8] = {b0.x, b0.y, b0.z, b0.w, b1.x, b1.y, b1.z, b1.w};
#pragma unroll
            for (int i = 0; i < 8; i++)
#pragma unroll
                for (int j = 0; j < 8; j++)
                    acc[i][j] = fmaf(a[i], b[j], acc[i][j]);
        }
        __syncthreads();
    }

    float bv[8];
#pragma unroll
    for (int j = 0; j < 8; j++) bv[j] = bias ? bias[bn + tCol + j] : 0.f;

#pragma unroll
    for (int i = 0; i < 8; i++) {
#pragma unroll
        for (int j = 0; j < 8; j++) {
            float v = acc[i][j] + bv[j];
            if (EPI == 1) v = 1.f / (1.f + expf(-v));
            acc[i][j] = v;
        }
        float4* cp = (float4*)(C + (size_t)(bm + tRow + i) * N + bn + tCol);
        cp[0] = make_float4(acc[i][0], acc[i][1], acc[i][2], acc[i][3]);
        cp[1] = make_float4(acc[i][4], acc[i][5], acc[i][6], acc[i][7]);
    }
}

// ---------------------------------------------------------------------------
// Grid barrier primitives (release/acquire on a monotonic counter)
// ---------------------------------------------------------------------------
__device__ __forceinline__ void red_release_add1(unsigned* p) {
    asm volatile("red.release.gpu.global.add.u32 [%0], 1;" :: "l"(p) : "memory");
}
__device__ __forceinline__ unsigned ld_acquire(const unsigned* p) {
    unsigned v;
    asm volatile("ld.acquire.gpu.global.u32 %0, [%1];" : "=r"(v) : "l"(p) : "memory");
    return v;
}

// ---------------------------------------------------------------------------
// Persistent scan kernel.
// 128 CTAs x 256 threads. CTA owns 8 output dims (eBase..eBase+7).
// A-slice held in registers: warp w owns k-segment [128w, 128w+128),
// lane l owns 4 consecutive k (float4) for all 8 e's -> 32 regs of A.
// Per step: 8 LDG.128 of s (L2) + 256 FFMA + 5-round warp halving reduce
// + cross-warp SMEM reduce + epilogue + grid barrier.
// ---------------------------------------------------------------------------
__global__ __launch_bounds__(256, 1)
void scan_kernel(const float* __restrict__ A)
{
    const int tid   = threadIdx.x;
    const int w     = tid >> 5;
    const int l     = tid & 31;
    const int eBase = blockIdx.x * EPER;
    const int dBase = w * 128 + l * 4;

    __shared__ float red[8][64];

    // Stationary A fragment: a[e] = A[eBase+e][dBase..dBase+3]
    float4 a[8];
#pragma unroll
    for (int e = 0; e < 8; e++)
        a[e] = *(const float4*)(A + (size_t)(eBase + e) * DIMD + dBase);

    // Epilogue thread mapping (threads 0..63 own one (b,e) output each)
    const int o   = tid;
    const int b_o = o >> 3;
    const int e_o = o & 7;

    float u_r = 0.f, g_r = 0.f, i_r = 0.f;
    if (tid < 64) {
        size_t idx0 = (size_t)b_o * SEQ * DIMD + (size_t)(eBase + e_o);
        u_r = g_u[idx0]; g_r = g_gate[idx0]; i_r = g_inp[idx0];
    }

    for (int t = 0; t < SEQ; t++) {
        const float* scur = g_s[t & 1];

        // --- dot-product partials: v[b*8+e] over this lane's 4 k's ---
        float4 s4[8];
#pragma unroll
        for (int b = 0; b < 8; b++)
            s4[b] = __ldcg((const float4*)(scur + b * DIMD + dBase));

        float v[64];
#pragma unroll
        for (int b = 0; b < 8; b++) {
#pragma unroll
            for (int e = 0; e < 8; e++) {
                float acc;
                acc = s4[b].x * a[e].x;
                acc = fmaf(s4[b].y, a[e].y, acc);
                acc = fmaf(s4[b].z, a[e].z, acc);
                acc = fmaf(s4[b].w, a[e].w, acc);
                v[b * 8 + e] = acc;
            }
        }

        // --- intra-warp halving reduction: lane l ends with totals for
        //     outputs o = 2l and 2l+1 (summed across all 32 lanes) ---
#pragma unroll
        for (int r = 0; r < 5; r++) {
            const int stride = 16 >> r;
            const int half   = 32 >> r;
            const bool hi    = (l & stride) != 0;
#pragma unroll
            for (int i = 0; i < half; i++) {
                float send = hi ? v[i] : v[half + i];
                float recv = __shfl_xor_sync(0xffffffffu, send, stride);
                float keep = hi ? v[half + i] : v[i];
                v[i] = keep + recv;
            }
        }

        // --- cross-warp (k-segment) reduction via SMEM ---
        *(float2*)&red[w][2 * l] = make_float2(v[0], v[1]);
        __syncthreads();

        if (tid < 64) {
            float y = 0.f;
#pragma unroll
            for (int ww = 0; ww < 8; ww++) y += red[ww][o];

            float sv = tanhf(y + u_r);
            sv = g_r * sv + (1.f - g_r) * i_r;

            g_s[(t + 1) & 1][b_o * DIMD + eBase + e_o] = sv;
            g_states[((size_t)b_o * SEQ + t) * DIMD + eBase + e_o] = sv;

            // prefetch next step's epilogue operands (hidden under next FMA loop)
            if (t + 1 < SEQ) {
                size_t idx = ((size_t)b_o * SEQ + (t + 1)) * DIMD + (eBase + e_o);
                u_r = g_u[idx]; g_r = g_gate[idx]; i_r = g_inp[idx];
            }
        }

        // --- grid barrier: all CTAs finish step t before anyone starts t+1 ---
        __syncthreads();
        if (tid == 0) {
            red_release_add1(&g_counter);
            const unsigned target = (unsigned)NSCAN * (unsigned)(t + 1);
            while (ld_acquire(&g_counter) < target) { }
        }
        __syncthreads();
    }
}

// ---------------------------------------------------------------------------
// kernel_launch: init -> 3 projection GEMMs -> scan -> output GEMM
// Inputs (metadata order): x, A, B, W_in, b_in, W_gate, b_gate, W_out, b_out
// ---------------------------------------------------------------------------
extern "C" void kernel_launch(void* const* d_in, const int* in_sizes, int n_in,
                              void* d_out, int out_size)
{
    (void)in_sizes; (void)n_in; (void)out_size;

    const float* x      = (const float*)d_in[0];
    const float* A      = (const float*)d_in[1];
    const float* Bmat   = (const float*)d_in[2];
    const float* W_in   = (const float*)d_in[3];
    const float* b_in   = (const float*)d_in[4];
    const float* W_gate = (const float*)d_in[5];
    const float* b_gate = (const float*)d_in[6];
    const float* W_out  = (const float*)d_in[7];
    const float* b_out  = (const float*)d_in[8];
    float* out          = (float*)d_out;

    void *p_inp, *p_gate, *p_u, *p_states;
    cudaGetSymbolAddress(&p_inp,    g_inp);
    cudaGetSymbolAddress(&p_gate,   g_gate);
    cudaGetSymbolAddress(&p_u,      g_u);
    cudaGetSymbolAddress(&p_states, g_states);

    float* inp    = (float*)p_inp;
    float* gate   = (float*)p_gate;
    float* u      = (float*)p_u;
    float* states = (float*)p_states;

    // 0) reset state + barrier counter (required for graph replay determinism)
    init_kernel<<<(BATCH * DIMD + 255) / 256, 256>>>();

    dim3 gg(DIMD / BN, MTOT / BM);   // (8, 256)

    // 1) inp = x @ W_in^T + b_in
    gemm_nt<0><<<gg, 256>>>(x, W_in, b_in, inp, MTOT, DIMD, DIMD);
    // 2) gate = sigmoid(inp @ W_gate^T + b_gate)
    gemm_nt<1><<<gg, 256>>>(inp, W_gate, b_gate, gate, MTOT, DIMD, DIMD);
    // 3) u = inp @ B^T
    gemm_nt<0><<<gg, 256>>>(inp, Bmat, nullptr, u, MTOT, DIMD, DIMD);
    // 4) sequential scan over 4096 timesteps
    scan_kernel<<<NSCAN, 256>>>(A);
    // 5) out = states @ W_out^T + b_out
    gemm_nt<0><<<gg, 256>>>(states, W_out, b_out, out, MTOT, DIMD, DIMD);
}

// round 4
// speedup vs baseline: 1.2618x; 1.2618x over previous
#include <cuda_runtime.h>
#include <math.h>
#include <stdint.h>

// ---------------------------------------------------------------------------
// Problem constants
// ---------------------------------------------------------------------------
#define DIMD  1024
#define BATCH 8
#define SEQ   4096
#define MTOT  (BATCH * SEQ)
#define NSCAN 128
#define EPER  (DIMD / NSCAN)

// ---------------------------------------------------------------------------
// Scratch (device-global; no allocation allowed)
// ---------------------------------------------------------------------------
__device__ float g_inp   [(size_t)MTOT * DIMD];
__device__ float g_gate  [(size_t)MTOT * DIMD];
__device__ float g_u     [(size_t)MTOT * DIMD];
__device__ float g_states[(size_t)MTOT * DIMD];
__device__ float g_s[2][BATCH * DIMD];
__device__ unsigned g_counter;

// ---------------------------------------------------------------------------
// Helpers
// ---------------------------------------------------------------------------
__device__ __forceinline__ uint32_t smem_u32(const void* p) {
    uint32_t a;
    asm("{ .reg .u64 t; cvta.to.shared.u64 t, %1; cvt.u32.u64 %0, t; }" : "=r"(a) : "l"(p));
    return a;
}

#define LDSM4(r, addr)                                                        \
    asm volatile("ldmatrix.sync.aligned.m8n8.x4.shared.b16 {%0,%1,%2,%3}, [%4];" \
        : "=r"((r)[0]), "=r"((r)[1]), "=r"((r)[2]), "=r"((r)[3]) : "r"(addr))

#define MMA16816(d, a, b)                                                     \
    asm volatile("mma.sync.aligned.m16n8k16.row.col.f32.bf16.bf16.f32 "       \
        "{%0,%1,%2,%3}, {%4,%5,%6,%7}, {%8,%9}, {%0,%1,%2,%3};"               \
        : "+f"((d)[0]), "+f"((d)[1]), "+f"((d)[2]), "+f"((d)[3])              \
        : "r"((a)[0]), "r"((a)[1]), "r"((a)[2]), "r"((a)[3]),                 \
          "r"((b)[0]), "r"((b)[1]))

// hi = bf16-truncation of two f32s, packed (x0 -> low half, x1 -> high half)
__device__ __forceinline__ uint32_t hipack(float x0, float x1) {
    return __byte_perm(__float_as_uint(x0), __float_as_uint(x1), 0x7632);
}
// lo = round-to-nearest bf16 of residuals, packed {lo0 low, lo1 high}
__device__ __forceinline__ uint32_t lopack(float x0, float x1) {
    float t0 = __uint_as_float(__float_as_uint(x0) & 0xFFFF0000u);
    float t1 = __uint_as_float(__float_as_uint(x1) & 0xFFFF0000u);
    float r0 = x0 - t0, r1 = x1 - t1;
    uint32_t d;
    asm("cvt.rn.bf16x2.f32 %0, %1, %2;" : "=r"(d) : "f"(r1), "f"(r0));
    return d;
}
__device__ __forceinline__ void split8(const float4& a, const float4& b,
                                       uint4& hi, uint4& lo) {
    hi.x = hipack(a.x, a.y); hi.y = hipack(a.z, a.w);
    hi.z = hipack(b.x, b.y); hi.w = hipack(b.z, b.w);
    lo.x = lopack(a.x, a.y); lo.y = lopack(a.z, a.w);
    lo.z = lopack(b.x, b.y); lo.w = lopack(b.z, b.w);
}

// XOR swizzle: 32B rows, 16B halves swap every 4 rows -> conflict-free STS/LDSM
__device__ __forceinline__ uint32_t swz(int row, int half) {
    return (uint32_t)(row * 32 + ((half ^ ((row >> 2) & 1)) << 4));
}

// ---------------------------------------------------------------------------
// Init kernel
// ---------------------------------------------------------------------------
__global__ void init_kernel() {
    int t = blockIdx.x * blockDim.x + threadIdx.x;
    if (t < BATCH * DIMD) { g_s[0][t] = 0.f; g_s[1][t] = 0.f; }
    if (t == 0) g_counter = 0u;
}

// ---------------------------------------------------------------------------
// bf16 3x-split tensor-core GEMM (NT): C[m][n] = sum_k X[m][k]*W[n][k] (+bias)(+sigmoid)
// CTA tile 128x128, K-chunk 16, 8 warps (warp tile 64x32), double-buffered SMEM.
// ---------------------------------------------------------------------------
#define GK 1024
#define GN 1024
#define NCHUNK (GK / 16)   // 64

template <int EPI>   // 0 = none, 1 = sigmoid
__global__ __launch_bounds__(256)
void gemm_mma(const float* __restrict__ X, const float* __restrict__ W,
              const float* __restrict__ bias, float* __restrict__ C)
{
    // [stage][tile: 0=Ahi 1=Alo 2=Bhi 3=Blo][4096 bytes]
    __shared__ __align__(1024) unsigned char sm[2][4][4096];

    const int tid = threadIdx.x;
    const int wid = tid >> 5, l = tid & 31;
    const int bm = blockIdx.y * 128, bn = blockIdx.x * 128;
    const int wm = wid & 1, wn = wid >> 1;   // warp grid 2 (M) x 4 (N)

    // --- global->smem mapping: thread owns (row = tid/2, 16B-half = tid&1)
    const int srow = tid >> 1, shalf = tid & 1;
    const float* Xp = X + (size_t)(bm + srow) * GK + shalf * 8;
    const float* Wp = W + (size_t)(bn + srow) * GK + shalf * 8;
    const uint32_t soff = swz(srow, shalf);

    // --- ldmatrix lane offsets
    // lanes 0-15 -> rows r+0..15 (k-half 0), lanes 16-31 -> rows r+0..15 (k-half 1)
    const int lrow = l & 15, lhalf = l >> 4;
    uint32_t offA[4], offB[2];
#pragma unroll
    for (int mi = 0; mi < 4; mi++) offA[mi] = swz(wm * 64 + mi * 16 + lrow, lhalf);
#pragma unroll
    for (int gi = 0; gi < 2; gi++) offB[gi] = swz(wn * 32 + gi * 16 + lrow, lhalf);

    const uint32_t smbase = smem_u32(&sm[0][0][0]);

    float acc[4][4][4];
#pragma unroll
    for (int mi = 0; mi < 4; mi++)
#pragma unroll
        for (int ni = 0; ni < 4; ni++)
#pragma unroll
            for (int r = 0; r < 4; r++) acc[mi][ni][r] = 0.f;

    // --- prologue: chunk 0 -> stage 0
    {
        float4 a0 = *(const float4*)(Xp + 0), a1 = *(const float4*)(Xp + 4);
        float4 b0 = *(const float4*)(Wp + 0), b1 = *(const float4*)(Wp + 4);
        uint4 hiA, loA, hiB, loB;
        split8(a0, a1, hiA, loA);
        split8(b0, b1, hiB, loB);
        *(uint4*)(&sm[0][0][soff]) = hiA;
        *(uint4*)(&sm[0][1][soff]) = loA;
        *(uint4*)(&sm[0][2][soff]) = hiB;
        *(uint4*)(&sm[0][3][soff]) = loB;
    }
    __syncthreads();

    for (int c = 0; c < NCHUNK; c++) {
        // prefetch next chunk into registers
        float4 na0, na1, nb0, nb1;
        if (c + 1 < NCHUNK) {
            const int kc = (c + 1) * 16;
            na0 = *(const float4*)(Xp + kc);     na1 = *(const float4*)(Xp + kc + 4);
            nb0 = *(const float4*)(Wp + kc);     nb1 = *(const float4*)(Wp + kc + 4);
        }

        const uint32_t sb = smbase + (uint32_t)(c & 1) * 16384u;

        // --- load fragments
        // A: ldmatrix.x4 order == {a0,a1,a2,a3} of the mma directly
        uint32_t ah[4][4], al[4][4];
#pragma unroll
        for (int mi = 0; mi < 4; mi++) {
            LDSM4(ah[mi], sb + 0 * 4096u + offA[mi]);
            LDSM4(al[mi], sb + 1 * 4096u + offA[mi]);
        }
        // B: [n][k] rows ARE col-major kxn; non-trans ldmatrix gives the
        // fragment directly. t[0]=n0..7/k0..7, t[1]=n8..15/k0..7,
        // t[2]=n0..7/k8..15, t[3]=n8..15/k8..15.
        uint32_t bh[4][2], bl[4][2];
#pragma unroll
        for (int gi = 0; gi < 2; gi++) {
            uint32_t t[4];
            LDSM4(t, sb + 2 * 4096u + offB[gi]);
            bh[2 * gi + 0][0] = t[0]; bh[2 * gi + 0][1] = t[2];
            bh[2 * gi + 1][0] = t[1]; bh[2 * gi + 1][1] = t[3];
            LDSM4(t, sb + 3 * 4096u + offB[gi]);
            bl[2 * gi + 0][0] = t[0]; bl[2 * gi + 0][1] = t[2];
            bl[2 * gi + 1][0] = t[1]; bl[2 * gi + 1][1] = t[3];
        }

        // --- 3-split MMAs (hh, hl, lh)
#pragma unroll
        for (int mi = 0; mi < 4; mi++)
#pragma unroll
            for (int ni = 0; ni < 4; ni++)
                MMA16816(acc[mi][ni], ah[mi], bh[ni]);
#pragma unroll
        for (int mi = 0; mi < 4; mi++)
#pragma unroll
            for (int ni = 0; ni < 4; ni++)
                MMA16816(acc[mi][ni], ah[mi], bl[ni]);
#pragma unroll
        for (int mi = 0; mi < 4; mi++)
#pragma unroll
            for (int ni = 0; ni < 4; ni++)
                MMA16816(acc[mi][ni], al[mi], bh[ni]);

        // --- store next chunk to the other stage
        if (c + 1 < NCHUNK) {
            __syncthreads();   // all reads of stage (c+1)&1 are done
            const int s = (c + 1) & 1;
            uint4 hiA, loA, hiB, loB;
            split8(na0, na1, hiA, loA);
            split8(nb0, nb1, hiB, loB);
            *(uint4*)(&sm[s][0][soff]) = hiA;
            *(uint4*)(&sm[s][1][soff]) = loA;
            *(uint4*)(&sm[s][2][soff]) = hiB;
            *(uint4*)(&sm[s][3][soff]) = loB;
            __syncthreads();   // stores visible
        }
    }

    // --- epilogue (D fragment: rows l/4 and l/4+8, cols 2*(l%4)+{0,1})
    const int erow  = bm + wm * 64 + (l >> 2);
    const int ecol0 = bn + wn * 32 + 2 * (l & 3);

    float2 bv[4];
#pragma unroll
    for (int ni = 0; ni < 4; ni++) {
        if (bias) {
            bv[ni].x = bias[ecol0 + ni * 8];
            bv[ni].y = bias[ecol0 + ni * 8 + 1];
        } else {
            bv[ni].x = 0.f; bv[ni].y = 0.f;
        }
    }

#pragma unroll
    for (int mi = 0; mi < 4; mi++) {
#pragma unroll
        for (int ni = 0; ni < 4; ni++) {
            const int r = erow + mi * 16;
            float2 v0, v1;
            v0.x = acc[mi][ni][0] + bv[ni].x;
            v0.y = acc[mi][ni][1] + bv[ni].y;
            v1.x = acc[mi][ni][2] + bv[ni].x;
            v1.y = acc[mi][ni][3] + bv[ni].y;
            if (EPI == 1) {
                v0.x = 1.f / (1.f + expf(-v0.x));
                v0.y = 1.f / (1.f + expf(-v0.y));
                v1.x = 1.f / (1.f + expf(-v1.x));
                v1.y = 1.f / (1.f + expf(-v1.y));
            }
            *(float2*)(C + (size_t)r * GN + ecol0 + ni * 8)       = v0;
            *(float2*)(C + (size_t)(r + 8) * GN + ecol0 + ni * 8) = v1;
        }
    }
}

// ---------------------------------------------------------------------------
// Grid barrier primitives
// ---------------------------------------------------------------------------
__device__ __forceinline__ void red_release_add1(unsigned* p) {
    asm volatile("red.release.gpu.global.add.u32 [%0], 1;" :: "l"(p) : "memory");
}
__device__ __forceinline__ unsigned ld_acquire(const unsigned* p) {
    unsigned v;
    asm volatile("ld.acquire.gpu.global.u32 %0, [%1];" : "=r"(v) : "l"(p) : "memory");
    return v;
}

// ---------------------------------------------------------------------------
// Persistent scan kernel (unchanged)
// ---------------------------------------------------------------------------
__global__ __launch_bounds__(256, 1)
void scan_kernel(const float* __restrict__ A)
{
    const int tid   = threadIdx.x;
    const int w     = tid >> 5;
    const int l     = tid & 31;
    const int eBase = blockIdx.x * EPER;
    const int dBase = w * 128 + l * 4;

    __shared__ float red[8][64];

    float4 a[8];
#pragma unroll
    for (int e = 0; e < 8; e++)
        a[e] = *(const float4*)(A + (size_t)(eBase + e) * DIMD + dBase);

    const int o   = tid;
    const int b_o = o >> 3;
    const int e_o = o & 7;

    float u_r = 0.f, g_r = 0.f, i_r = 0.f;
    if (tid < 64) {
        size_t idx0 = (size_t)b_o * SEQ * DIMD + (size_t)(eBase + e_o);
        u_r = g_u[idx0]; g_r = g_gate[idx0]; i_r = g_inp[idx0];
    }

    for (int t = 0; t < SEQ; t++) {
        const float* scur = g_s[t & 1];

        float4 s4[8];
#pragma unroll
        for (int b = 0; b < 8; b++)
            s4[b] = __ldcg((const float4*)(scur + b * DIMD + dBase));

        float v[64];
#pragma unroll
        for (int b = 0; b < 8; b++) {
#pragma unroll
            for (int e = 0; e < 8; e++) {
                float acc;
                acc = s4[b].x * a[e].x;
                acc = fmaf(s4[b].y, a[e].y, acc);
                acc = fmaf(s4[b].z, a[e].z, acc);
                acc = fmaf(s4[b].w, a[e].w, acc);
                v[b * 8 + e] = acc;
            }
        }

#pragma unroll
        for (int r = 0; r < 5; r++) {
            const int stride = 16 >> r;
            const int half   = 32 >> r;
            const bool hi    = (l & stride) != 0;
#pragma unroll
            for (int i = 0; i < half; i++) {
                float send = hi ? v[i] : v[half + i];
                float recv = __shfl_xor_sync(0xffffffffu, send, stride);
                float keep = hi ? v[half + i] : v[i];
                v[i] = keep + recv;
            }
        }

        *(float2*)&red[w][2 * l] = make_float2(v[0], v[1]);
        __syncthreads();

        if (tid < 64) {
            float y = 0.f;
#pragma unroll
            for (int ww = 0; ww < 8; ww++) y += red[ww][o];

            float sv = tanhf(y + u_r);
            sv = g_r * sv + (1.f - g_r) * i_r;

            g_s[(t + 1) & 1][b_o * DIMD + eBase + e_o] = sv;
            g_states[((size_t)b_o * SEQ + t) * DIMD + eBase + e_o] = sv;

            if (t + 1 < SEQ) {
                size_t idx = ((size_t)b_o * SEQ + (t + 1)) * DIMD + (eBase + e_o);
                u_r = g_u[idx]; g_r = g_gate[idx]; i_r = g_inp[idx];
            }
        }

        __syncthreads();
        if (tid == 0) {
            red_release_add1(&g_counter);
            const unsigned target = (unsigned)NSCAN * (unsigned)(t + 1);
            while (ld_acquire(&g_counter) < target) { }
        }
        __syncthreads();
    }
}

// ---------------------------------------------------------------------------
// kernel_launch
// ---------------------------------------------------------------------------
extern "C" void kernel_launch(void* const* d_in, const int* in_sizes, int n_in,
                              void* d_out, int out_size)
{
    (void)in_sizes; (void)n_in; (void)out_size;

    const float* x      = (const float*)d_in[0];
    const float* A      = (const float*)d_in[1];
    const float* Bmat   = (const float*)d_in[2];
    const float* W_in   = (const float*)d_in[3];
    const float* b_in   = (const float*)d_in[4];
    const float* W_gate = (const float*)d_in[5];
    const float* b_gate = (const float*)d_in[6];
    const float* W_out  = (const float*)d_in[7];
    const float* b_out  = (const float*)d_in[8];
    float* out          = (float*)d_out;

    void *p_inp, *p_gate, *p_u, *p_states;
    cudaGetSymbolAddress(&p_inp,    g_inp);
    cudaGetSymbolAddress(&p_gate,   g_gate);
    cudaGetSymbolAddress(&p_u,      g_u);
    cudaGetSymbolAddress(&p_states, g_states);

    float* inp    = (float*)p_inp;
    float* gate   = (float*)p_gate;
    float* u      = (float*)p_u;
    float* states = (float*)p_states;

    init_kernel<<<(BATCH * DIMD + 255) / 256, 256>>>();

    dim3 gg(DIMD / 128, MTOT / 128);   // (8, 256)

    gemm_mma<0><<<gg, 256>>>(x, W_in, b_in, inp);
    gemm_mma<1><<<gg, 256>>>(inp, W_gate, b_gate, gate);
    gemm_mma<0><<<gg, 256>>>(inp, Bmat, nullptr, u);
    scan_kernel<<<NSCAN, 256>>>(A);
    gemm_mma<0><<<gg, 256>>>(states, W_out, b_out, out);
}

// round 5
// speedup vs baseline: 1.3067x; 1.0356x over previous
#include <cuda_runtime.h>
#include <math.h>
#include <stdint.h>

// ---------------------------------------------------------------------------
// Problem constants
// ---------------------------------------------------------------------------
#define DIMD  1024
#define BATCH 8
#define SEQ   4096
#define MTOT  (BATCH * SEQ)
#define NSCAN 128
#define EPER  (DIMD / NSCAN)   // 8

// ---------------------------------------------------------------------------
// Scratch (device-global; no allocation allowed)
// ---------------------------------------------------------------------------
__device__ float    g_inp   [(size_t)MTOT * DIMD];
__device__ float    g_gate  [(size_t)MTOT * DIMD];
__device__ float    g_u     [(size_t)MTOT * DIMD];
__device__ float    g_states[(size_t)MTOT * DIMD];
__device__ uint32_t g_sp[2][BATCH * DIMD];   // ping-pong state, packed (bf16 hi | bf16 lo<<16)
__device__ unsigned g_counter;

// ---------------------------------------------------------------------------
// Helpers
// ---------------------------------------------------------------------------
__device__ __forceinline__ uint32_t smem_u32(const void* p) {
    uint32_t a;
    asm("{ .reg .u64 t; cvta.to.shared.u64 t, %1; cvt.u32.u64 %0, t; }" : "=r"(a) : "l"(p));
    return a;
}

#define LDSM4(r, addr)                                                        \
    asm volatile("ldmatrix.sync.aligned.m8n8.x4.shared.b16 {%0,%1,%2,%3}, [%4];" \
        : "=r"((r)[0]), "=r"((r)[1]), "=r"((r)[2]), "=r"((r)[3]) : "r"(addr))

#define MMA16816(d, a, b)                                                     \
    asm volatile("mma.sync.aligned.m16n8k16.row.col.f32.bf16.bf16.f32 "       \
        "{%0,%1,%2,%3}, {%4,%5,%6,%7}, {%8,%9}, {%0,%1,%2,%3};"               \
        : "+f"((d)[0]), "+f"((d)[1]), "+f"((d)[2]), "+f"((d)[3])              \
        : "r"((a)[0]), "r"((a)[1]), "r"((a)[2]), "r"((a)[3]),                 \
          "r"((b)[0]), "r"((b)[1]))

// hi = bf16-truncation of two f32s, packed (x0 -> low half, x1 -> high half)
__device__ __forceinline__ uint32_t hipack(float x0, float x1) {
    return __byte_perm(__float_as_uint(x0), __float_as_uint(x1), 0x7632);
}
// lo = round-to-nearest bf16 of residuals, packed {lo0 low, lo1 high}
__device__ __forceinline__ uint32_t lopack(float x0, float x1) {
    float t0 = __uint_as_float(__float_as_uint(x0) & 0xFFFF0000u);
    float t1 = __uint_as_float(__float_as_uint(x1) & 0xFFFF0000u);
    float r0 = x0 - t0, r1 = x1 - t1;
    uint32_t d;
    asm("cvt.rn.bf16x2.f32 %0, %1, %2;" : "=r"(d) : "f"(r1), "f"(r0));
    return d;
}
__device__ __forceinline__ void split8(const float4& a, const float4& b,
                                       uint4& hi, uint4& lo) {
    hi.x = hipack(a.x, a.y); hi.y = hipack(a.z, a.w);
    hi.z = hipack(b.x, b.y); hi.w = hipack(b.z, b.w);
    lo.x = lopack(a.x, a.y); lo.y = lopack(a.z, a.w);
    lo.z = lopack(b.x, b.y); lo.w = lopack(b.z, b.w);
}

// XOR swizzle for GEMM tiles: 32B rows, 16B halves swap every 4 rows
__device__ __forceinline__ uint32_t swz(int row, int half) {
    return (uint32_t)(row * 32 + ((half ^ ((row >> 2) & 1)) << 4));
}

__device__ __forceinline__ uint4 ldcg4(const uint4* p) {
    uint4 v;
    asm volatile("ld.global.cg.v4.u32 {%0,%1,%2,%3}, [%4];"
                 : "=r"(v.x), "=r"(v.y), "=r"(v.z), "=r"(v.w) : "l"(p));
    return v;
}

// ---------------------------------------------------------------------------
// Init kernel: zero packed state buffers + barrier counter
// ---------------------------------------------------------------------------
__global__ void init_kernel() {
    int t = blockIdx.x * blockDim.x + threadIdx.x;
    if (t < BATCH * DIMD) { g_sp[0][t] = 0u; g_sp[1][t] = 0u; }
    if (t == 0) g_counter = 0u;
}

// ---------------------------------------------------------------------------
// bf16 3x-split tensor-core GEMM (unchanged from R4, passing at 622us)
// ---------------------------------------------------------------------------
#define GK 1024
#define GN 1024
#define NCHUNK (GK / 16)   // 64

template <int EPI>   // 0 = none, 1 = sigmoid
__global__ __launch_bounds__(256)
void gemm_mma(const float* __restrict__ X, const float* __restrict__ W,
              const float* __restrict__ bias, float* __restrict__ C)
{
    __shared__ __align__(1024) unsigned char sm[2][4][4096];

    const int tid = threadIdx.x;
    const int wid = tid >> 5, l = tid & 31;
    const int bm = blockIdx.y * 128, bn = blockIdx.x * 128;
    const int wm = wid & 1, wn = wid >> 1;

    const int srow = tid >> 1, shalf = tid & 1;
    const float* Xp = X + (size_t)(bm + srow) * GK + shalf * 8;
    const float* Wp = W + (size_t)(bn + srow) * GK + shalf * 8;
    const uint32_t soff = swz(srow, shalf);

    const int lrow = l & 15, lhalf = l >> 4;
    uint32_t offA[4], offB[2];
#pragma unroll
    for (int mi = 0; mi < 4; mi++) offA[mi] = swz(wm * 64 + mi * 16 + lrow, lhalf);
#pragma unroll
    for (int gi = 0; gi < 2; gi++) offB[gi] = swz(wn * 32 + gi * 16 + lrow, lhalf);

    const uint32_t smbase = smem_u32(&sm[0][0][0]);

    float acc[4][4][4];
#pragma unroll
    for (int mi = 0; mi < 4; mi++)
#pragma unroll
        for (int ni = 0; ni < 4; ni++)
#pragma unroll
            for (int r = 0; r < 4; r++) acc[mi][ni][r] = 0.f;

    {
        float4 a0 = *(const float4*)(Xp + 0), a1 = *(const float4*)(Xp + 4);
        float4 b0 = *(const float4*)(Wp + 0), b1 = *(const float4*)(Wp + 4);
        uint4 hiA, loA, hiB, loB;
        split8(a0, a1, hiA, loA);
        split8(b0, b1, hiB, loB);
        *(uint4*)(&sm[0][0][soff]) = hiA;
        *(uint4*)(&sm[0][1][soff]) = loA;
        *(uint4*)(&sm[0][2][soff]) = hiB;
        *(uint4*)(&sm[0][3][soff]) = loB;
    }
    __syncthreads();

    for (int c = 0; c < NCHUNK; c++) {
        float4 na0, na1, nb0, nb1;
        if (c + 1 < NCHUNK) {
            const int kc = (c + 1) * 16;
            na0 = *(const float4*)(Xp + kc);     na1 = *(const float4*)(Xp + kc + 4);
            nb0 = *(const float4*)(Wp + kc);     nb1 = *(const float4*)(Wp + kc + 4);
        }

        const uint32_t sb = smbase + (uint32_t)(c & 1) * 16384u;

        uint32_t ah[4][4], al[4][4];
#pragma unroll
        for (int mi = 0; mi < 4; mi++) {
            LDSM4(ah[mi], sb + 0 * 4096u + offA[mi]);
            LDSM4(al[mi], sb + 1 * 4096u + offA[mi]);
        }
        uint32_t bh[4][2], bl[4][2];
#pragma unroll
        for (int gi = 0; gi < 2; gi++) {
            uint32_t t[4];
            LDSM4(t, sb + 2 * 4096u + offB[gi]);
            bh[2 * gi + 0][0] = t[0]; bh[2 * gi + 0][1] = t[2];
            bh[2 * gi + 1][0] = t[1]; bh[2 * gi + 1][1] = t[3];
            LDSM4(t, sb + 3 * 4096u + offB[gi]);
            bl[2 * gi + 0][0] = t[0]; bl[2 * gi + 0][1] = t[2];
            bl[2 * gi + 1][0] = t[1]; bl[2 * gi + 1][1] = t[3];
        }

#pragma unroll
        for (int mi = 0; mi < 4; mi++)
#pragma unroll
            for (int ni = 0; ni < 4; ni++)
                MMA16816(acc[mi][ni], ah[mi], bh[ni]);
#pragma unroll
        for (int mi = 0; mi < 4; mi++)
#pragma unroll
            for (int ni = 0; ni < 4; ni++)
                MMA16816(acc[mi][ni], ah[mi], bl[ni]);
#pragma unroll
        for (int mi = 0; mi < 4; mi++)
#pragma unroll
            for (int ni = 0; ni < 4; ni++)
                MMA16816(acc[mi][ni], al[mi], bh[ni]);

        if (c + 1 < NCHUNK) {
            __syncthreads();
            const int s = (c + 1) & 1;
            uint4 hiA, loA, hiB, loB;
            split8(na0, na1, hiA, loA);
            split8(nb0, nb1, hiB, loB);
            *(uint4*)(&sm[s][0][soff]) = hiA;
            *(uint4*)(&sm[s][1][soff]) = loA;
            *(uint4*)(&sm[s][2][soff]) = hiB;
            *(uint4*)(&sm[s][3][soff]) = loB;
            __syncthreads();
        }
    }

    const int erow  = bm + wm * 64 + (l >> 2);
    const int ecol0 = bn + wn * 32 + 2 * (l & 3);

    float2 bv[4];
#pragma unroll
    for (int ni = 0; ni < 4; ni++) {
        if (bias) {
            bv[ni].x = bias[ecol0 + ni * 8];
            bv[ni].y = bias[ecol0 + ni * 8 + 1];
        } else {
            bv[ni].x = 0.f; bv[ni].y = 0.f;
        }
    }

#pragma unroll
    for (int mi = 0; mi < 4; mi++) {
#pragma unroll
        for (int ni = 0; ni < 4; ni++) {
            const int r = erow + mi * 16;
            float2 v0, v1;
            v0.x = acc[mi][ni][0] + bv[ni].x;
            v0.y = acc[mi][ni][1] + bv[ni].y;
            v1.x = acc[mi][ni][2] + bv[ni].x;
            v1.y = acc[mi][ni][3] + bv[ni].y;
            if (EPI == 1) {
                v0.x = 1.f / (1.f + expf(-v0.x));
                v0.y = 1.f / (1.f + expf(-v0.y));
                v1.x = 1.f / (1.f + expf(-v1.x));
                v1.y = 1.f / (1.f + expf(-v1.y));
            }
            *(float2*)(C + (size_t)r * GN + ecol0 + ni * 8)       = v0;
            *(float2*)(C + (size_t)(r + 8) * GN + ecol0 + ni * 8) = v1;
        }
    }
}

// ---------------------------------------------------------------------------
// Grid barrier primitives
// ---------------------------------------------------------------------------
__device__ __forceinline__ void red_release_add1(unsigned* p) {
    asm volatile("red.release.gpu.global.add.u32 [%0], 1;" :: "l"(p) : "memory");
}
__device__ __forceinline__ unsigned ld_acquire(const unsigned* p) {
    unsigned v;
    asm volatile("ld.acquire.gpu.global.u32 %0, [%1];" : "=r"(v) : "l"(p) : "memory");
    return v;
}

// ---------------------------------------------------------------------------
// Tensor-core scan kernel.
// 128 CTAs x 256 threads. CTA owns 8 e-dims. Per step:
//   D(16x8) = s_frag(16pad x 1024, bf16 split) @ Amat_slice^T, via m16n8k16,
//   warp w covers k-seg [128w,128w+128) = 8 k16-chunks x 3 split products.
// Amat B-fragments are STATIONARY in registers (pre-split hi/lo).
// State communicated as packed (bf16hi | bf16lo<<16) words; unpacked to
// swizzled SMEM, fragments via ldmatrix.x4. Cross-warp reduce via SMEM.
// ---------------------------------------------------------------------------
#define SCAN_SMEM (32768 * 2 + 2048)   // s_hi[16][1024]bf16, s_lo, red[8][64]f32

__global__ __launch_bounds__(256, 1)
void scan_mma(const float* __restrict__ A)
{
    extern __shared__ unsigned char sms[];
    unsigned char* SH = sms;                    // 16 x 2048 B (rows 8-15 zero pad)
    unsigned char* SL = sms + 32768;
    float* RED        = (float*)(sms + 65536);  // [8][64]

    const int tid = threadIdx.x;
    const int w   = tid >> 5;
    const int l   = tid & 31;
    const int eBase = blockIdx.x * EPER;

    const uint32_t shb = smem_u32(SH);
    const uint32_t slb = smem_u32(SL);

    // zero pad rows 8..15 once (16 KB per tile)
    for (int i = tid * 16; i < 16384; i += 256 * 16) {
        *(uint4*)(SH + 16384 + i) = make_uint4(0, 0, 0, 0);
        *(uint4*)(SL + 16384 + i) = make_uint4(0, 0, 0, 0);
    }

    // --- stationary B fragments: B[k][n] = Amat[eBase+n][k], pre-split hi/lo
    uint32_t uH[8][2], uL[8][2];
    {
        const int e_row = eBase + (l >> 2);
#pragma unroll
        for (int j = 0; j < 8; j++) {
#pragma unroll
            for (int r = 0; r < 2; r++) {
                int k = 128 * w + 16 * j + 2 * (l & 3) + 8 * r;
                float2 av = *(const float2*)(A + (size_t)e_row * DIMD + k);
                uH[j][r] = hipack(av.x, av.y);
                uL[j][r] = lopack(av.x, av.y);
            }
        }
    }

    // --- ldmatrix lane geometry (A-operand, 16x16 tiles)
    const int g    = l >> 3;
    const int lrow = (g & 1) * 8 + (l & 7);
    const int lkh  = (g >> 1) & 1;
    const uint32_t lsw   = (uint32_t)((lrow & 7) << 4);
    const uint32_t cbase = (uint32_t)(256 * w + 16 * lkh);
    const uint32_t rowoff = (uint32_t)(lrow * 2048);

    // --- epilogue mapping (threads 0..63 own one (b,e) output)
    const int b_o = tid >> 3;
    const int e_o = tid & 7;

    float u_r = 0.f, g_r = 0.f, i_r = 0.f;
    if (tid < 64) {
        size_t idx0 = (size_t)b_o * SEQ * DIMD + (size_t)(eBase + e_o);
        u_r = g_u[idx0]; g_r = g_gate[idx0]; i_r = g_inp[idx0];
    }

    // --- state fill geometry: warp w loads batch row b=w
    const uint32_t stsw = (uint32_t)((w & 7) << 4);

    __syncthreads();   // zero-pad visible

    for (int t = 0; t < SEQ; t++) {
        // 1) load packed state row b=w (L2, bypass L1 - ping-pong staleness)
        const uint4* srow = (const uint4*)(&g_sp[t & 1][w * DIMD]);
        uint4 p[8];
#pragma unroll
        for (int i = 0; i < 8; i++) p[i] = ldcg4(srow + i * 32 + l);

        // 2) unpack to swizzled SMEM tiles (hi, lo)
#pragma unroll
        for (int i = 0; i < 8; i++) {
            uint32_t h0 = __byte_perm(p[i].x, p[i].y, 0x5410);
            uint32_t h1 = __byte_perm(p[i].z, p[i].w, 0x5410);
            uint32_t q0 = __byte_perm(p[i].x, p[i].y, 0x7632);
            uint32_t q1 = __byte_perm(p[i].z, p[i].w, 0x7632);
            uint32_t cb = ((uint32_t)(256 * i + 8 * l)) ^ stsw;
            *(uint2*)(SH + w * 2048 + cb) = make_uint2(h0, h1);
            *(uint2*)(SL + w * 2048 + cb) = make_uint2(q0, q1);
        }
        __syncthreads();

        // 3) 8 chunks x 3 split MMAs
        float acc0[4] = {0.f, 0.f, 0.f, 0.f};
        float acc1[4] = {0.f, 0.f, 0.f, 0.f};
#pragma unroll
        for (int j = 0; j < 8; j++) {
            uint32_t cb = (cbase + 32u * j) ^ lsw;
            uint32_t ah[4], as[4];
            LDSM4(ah, shb + rowoff + cb);
            LDSM4(as, slb + rowoff + cb);
            float* acc = (j & 1) ? acc1 : acc0;
            MMA16816(acc, ah, uH[j]);
            MMA16816(acc, ah, uL[j]);
            MMA16816(acc, as, uH[j]);
        }
        float c0 = acc0[0] + acc1[0];
        float c1 = acc0[1] + acc1[1];
        // D rows 8-15 are zero padding; regs 2,3 ignored.

        // 4) cross-warp reduce: lane holds outputs (b=l>>2, e=2(l&3)+{0,1})
        *(float2*)&RED[w * 64 + (l >> 2) * 8 + 2 * (l & 3)] = make_float2(c0, c1);
        __syncthreads();

        if (tid < 64) {
            float y = 0.f;
#pragma unroll
            for (int ww = 0; ww < 8; ww++) y += RED[ww * 64 + tid];

            float sv = tanhf(y + u_r);
            sv = g_r * sv + (1.f - g_r) * i_r;

            // fp32 states for the output GEMM
            g_states[((size_t)b_o * SEQ + t) * DIMD + eBase + e_o] = sv;

            // packed split state for next step
            uint32_t fui = __float_as_uint(sv);
            float resid = sv - __uint_as_float(fui & 0xFFFF0000u);
            uint32_t lo2;
            asm("cvt.rn.bf16x2.f32 %0, %1, %2;" : "=r"(lo2) : "f"(0.f), "f"(resid));
            uint32_t packed = (fui >> 16) | (lo2 << 16);
            g_sp[(t + 1) & 1][b_o * DIMD + eBase + e_o] = packed;

            if (t + 1 < SEQ) {
                size_t idx = ((size_t)b_o * SEQ + (t + 1)) * DIMD + (eBase + e_o);
                u_r = g_u[idx]; g_r = g_gate[idx]; i_r = g_inp[idx];
            }
        }

        // 5) grid barrier
        __syncthreads();
        if (tid == 0) {
            red_release_add1(&g_counter);
            const unsigned target = (unsigned)NSCAN * (unsigned)(t + 1);
            while (ld_acquire(&g_counter) < target) { }
        }
        __syncthreads();
    }
}

// ---------------------------------------------------------------------------
// kernel_launch
// ---------------------------------------------------------------------------
extern "C" void kernel_launch(void* const* d_in, const int* in_sizes, int n_in,
                              void* d_out, int out_size)
{
    (void)in_sizes; (void)n_in; (void)out_size;

    const float* x      = (const float*)d_in[0];
    const float* A      = (const float*)d_in[1];
    const float* Bmat   = (const float*)d_in[2];
    const float* W_in   = (const float*)d_in[3];
    const float* b_in   = (const float*)d_in[4];
    const float* W_gate = (const float*)d_in[5];
    const float* b_gate = (const float*)d_in[6];
    const float* W_out  = (const float*)d_in[7];
    const float* b_out  = (const float*)d_in[8];
    float* out          = (float*)d_out;

    void *p_inp, *p_gate, *p_u, *p_states;
    cudaGetSymbolAddress(&p_inp,    g_inp);
    cudaGetSymbolAddress(&p_gate,   g_gate);
    cudaGetSymbolAddress(&p_u,      g_u);
    cudaGetSymbolAddress(&p_states, g_states);

    float* inp    = (float*)p_inp;
    float* gate   = (float*)p_gate;
    float* u      = (float*)p_u;
    float* states = (float*)p_states;

    cudaFuncSetAttribute(scan_mma, cudaFuncAttributeMaxDynamicSharedMemorySize, SCAN_SMEM);

    init_kernel<<<(BATCH * DIMD + 255) / 256, 256>>>();

    dim3 gg(DIMD / 128, MTOT / 128);   // (8, 256)

    gemm_mma<0><<<gg, 256>>>(x, W_in, b_in, inp);
    gemm_mma<1><<<gg, 256>>>(inp, W_gate, b_gate, gate);
    gemm_mma<0><<<gg, 256>>>(inp, Bmat, nullptr, u);
    scan_mma<<<NSCAN, 256, SCAN_SMEM>>>(A);
    gemm_mma<0><<<gg, 256>>>(states, W_out, b_out, out);
}